// round 3
// baseline (speedup 1.0000x reference)
#include <cuda_runtime.h>

// ---------------- constants ----------------
namespace {
constexpr int B_  = 32;
constexpr int C_  = 384;
constexpr int H_  = 56;
constexpr int W_  = 56;
constexpr int WS_ = 7;
constexpr int NH_ = 12;
constexpr int N_  = 49;     // WS*WS
constexpr int TOK = B_ * H_ * W_;    // 100352
constexpr int HID_ = 4 * C_;         // 1536
constexpr int WINS = TOK / N_;       // 2048
}

// ---------------- scratch (device globals; no runtime allocation) ----------------
__device__ float g_xT[TOK * C_];     // x in (B,H,W,C) layout (shortcut)
__device__ float g_a[TOK * C_];      // xw_ln -> proj_out -> xn (reused)
__device__ float g_attn[TOK * C_];   // attention out -> final pre-transpose (reused)
__device__ float g_res[TOK * C_];    // residual after attention branch
__device__ float g_big[TOK * HID_];  // qkv (tok x 1152) then mlp hidden (tok x 1536)

// ---------------- f32x2 helpers ----------------
__device__ __forceinline__ unsigned long long ffma2(unsigned long long a,
                                                    unsigned long long b,
                                                    unsigned long long c) {
    unsigned long long d;
    asm("fma.rn.f32x2 %0, %1, %2, %3;" : "=l"(d) : "l"(a), "l"(b), "l"(c));
    return d;
}
__device__ __forceinline__ float lo32(unsigned long long v) {
    return __uint_as_float((unsigned int)(v & 0xffffffffULL));
}
__device__ __forceinline__ float hi32(unsigned long long v) {
    return __uint_as_float((unsigned int)(v >> 32));
}

// ---------------- tiled batch transpose: dst[b][col][row] = src[b][row][col] ----------------
__global__ void transpose_kernel(const float* __restrict__ src, float* __restrict__ dst,
                                 int rows, int cols) {
    __shared__ float t[32][33];
    int b = blockIdx.z;
    const float* s = src + (size_t)b * rows * cols;
    float* d = dst + (size_t)b * rows * cols;
    int c0 = blockIdx.x * 32, r0 = blockIdx.y * 32;
    int tx = threadIdx.x, ty = threadIdx.y;
#pragma unroll
    for (int i = 0; i < 32; i += 8)
        t[ty + i][tx] = s[(size_t)(r0 + ty + i) * cols + c0 + tx];
    __syncthreads();
#pragma unroll
    for (int i = 0; i < 32; i += 8)
        d[(size_t)(c0 + ty + i) * rows + r0 + tx] = t[tx][ty + i];
}

// ---------------- LayerNorm helpers ----------------
__device__ __forceinline__ void block_ln_stats_128(float x0, float x1, float x2,
                                                   float& mean, float& rstd) {
    __shared__ float red[8];
    float s = x0 + x1 + x2;
    float s2 = x0 * x0 + x1 * x1 + x2 * x2;
#pragma unroll
    for (int o = 16; o > 0; o >>= 1) {
        s  += __shfl_xor_sync(0xffffffffu, s, o);
        s2 += __shfl_xor_sync(0xffffffffu, s2, o);
    }
    int w = threadIdx.x >> 5;
    if ((threadIdx.x & 31) == 0) { red[w] = s; red[4 + w] = s2; }
    __syncthreads();
    s  = red[0] + red[1] + red[2] + red[3];
    s2 = red[4] + red[5] + red[6] + red[7];
    mean = s * (1.0f / 384.0f);
    float var = s2 * (1.0f / 384.0f) - mean * mean;
    rstd = rsqrtf(var + 1e-5f);
}

// shift (-3,-3) + window-partition + LN1: out row r = (win, n) order
__global__ __launch_bounds__(128) void ln_win_kernel(const float* __restrict__ xT,
                                                     const float* __restrict__ g,
                                                     const float* __restrict__ b,
                                                     float* __restrict__ out) {
    int r = blockIdx.x;
    int win = r / N_, n = r % N_;
    int bb = win >> 6, wi = win & 63;
    int wh = wi >> 3, ww = wi & 7;
    int i = n / WS_, j = n % WS_;
    int hs = (wh * WS_ + i + 3) % H_;   // shifted = roll(-3): src index = idx + 3
    int ws = (ww * WS_ + j + 3) % W_;
    const float* src = xT + ((size_t)(bb * H_ + hs) * W_ + ws) * C_;
    int t = threadIdx.x;
    float x0 = src[t], x1 = src[t + 128], x2 = src[t + 256];
    float mean, rstd;
    block_ln_stats_128(x0, x1, x2, mean, rstd);
    float* o = out + (size_t)r * C_;
    o[t]       = (x0 - mean) * rstd * g[t]       + b[t];
    o[t + 128] = (x1 - mean) * rstd * g[t + 128] + b[t + 128];
    o[t + 256] = (x2 - mean) * rstd * g[t + 256] + b[t + 256];
}

// plain LN over rows (token natural order)
__global__ __launch_bounds__(128) void ln_plain_kernel(const float* __restrict__ in,
                                                       const float* __restrict__ g,
                                                       const float* __restrict__ b,
                                                       float* __restrict__ out) {
    int r = blockIdx.x;
    const float* src = in + (size_t)r * C_;
    int t = threadIdx.x;
    float x0 = src[t], x1 = src[t + 128], x2 = src[t + 256];
    float mean, rstd;
    block_ln_stats_128(x0, x1, x2, mean, rstd);
    float* o = out + (size_t)r * C_;
    o[t]       = (x0 - mean) * rstd * g[t]       + b[t];
    o[t + 128] = (x1 - mean) * rstd * g[t + 128] + b[t + 128];
    o[t + 256] = (x2 - mean) * rstd * g[t + 256] + b[t + 256];
}

// ---------------- GEMM: C[M,N] = A[M,K] @ B[K,N] + bias, with epilogue ----------------
// epi: 0 = bias only, 1 = bias + exact GELU, 2 = bias + residual add
// Requires M%64==0, N%64==0, K%16==0.
__global__ __launch_bounds__(256) void gemm_kernel(const float* __restrict__ A,
                                                   const float* __restrict__ Bw,
                                                   const float* __restrict__ bias,
                                                   float* __restrict__ Cm,
                                                   const float* __restrict__ resid,
                                                   int M, int Nn, int K, int epi) {
    __shared__ __align__(16) float As[64][20];  // [m][k], padded
    __shared__ __align__(16) float Bs[64][20];  // [n][k] (transposed), padded
    int tid = threadIdx.x;
    int tx = tid & 15, ty = tid >> 4;
    int m0 = blockIdx.x * 64;
    int n0 = blockIdx.y * 64;

    int ar = tid >> 2;           // 0..63 (row of A tile)
    int ak = (tid & 3) << 2;     // 0,4,8,12
    int bk = tid >> 4;           // 0..15 (k row of B tile)
    int bn = (tid & 15) << 2;    // 0..60

    unsigned long long acc[4][4];
#pragma unroll
    for (int i = 0; i < 4; i++)
#pragma unroll
        for (int j = 0; j < 4; j++) acc[i][j] = 0ULL;

    for (int k0 = 0; k0 < K; k0 += 16) {
        float4 av = *(const float4*)(A + (size_t)(m0 + ar) * K + k0 + ak);
        *(float4*)&As[ar][ak] = av;
        float4 bv = *(const float4*)(Bw + (size_t)(k0 + bk) * Nn + n0 + bn);
        Bs[bn + 0][bk] = bv.x;
        Bs[bn + 1][bk] = bv.y;
        Bs[bn + 2][bk] = bv.z;
        Bs[bn + 3][bk] = bv.w;
        __syncthreads();
#pragma unroll
        for (int kc = 0; kc < 16; kc += 4) {
            ulonglong2 a2[4], b2[4];
#pragma unroll
            for (int i = 0; i < 4; i++)
                a2[i] = *(const ulonglong2*)&As[ty * 4 + i][kc];
#pragma unroll
            for (int j = 0; j < 4; j++)
                b2[j] = *(const ulonglong2*)&Bs[tx * 4 + j][kc];
#pragma unroll
            for (int i = 0; i < 4; i++)
#pragma unroll
                for (int j = 0; j < 4; j++) {
                    acc[i][j] = ffma2(a2[i].x, b2[j].x, acc[i][j]);
                    acc[i][j] = ffma2(a2[i].y, b2[j].y, acc[i][j]);
                }
        }
        __syncthreads();
    }

    // epilogue
#pragma unroll
    for (int i = 0; i < 4; i++) {
        size_t m = (size_t)(m0 + ty * 4 + i);
        int nbase = n0 + tx * 4;
        float v[4];
#pragma unroll
        for (int j = 0; j < 4; j++)
            v[j] = lo32(acc[i][j]) + hi32(acc[i][j]) + bias[nbase + j];
        if (epi == 1) {
#pragma unroll
            for (int j = 0; j < 4; j++)
                v[j] = 0.5f * v[j] * (1.0f + erff(v[j] * 0.70710678118654752f));
        } else if (epi == 2) {
            float4 rr = *(const float4*)(resid + m * Nn + nbase);
            v[0] += rr.x; v[1] += rr.y; v[2] += rr.z; v[3] += rr.w;
        }
        float4 o = make_float4(v[0], v[1], v[2], v[3]);
        *(float4*)(Cm + m * Nn + nbase) = o;
    }
}

// ---------------- fused window attention: one block per (window, head) ----------------
__global__ __launch_bounds__(256) void attn_kernel(const float* __restrict__ qkv,
                                                   const float* __restrict__ rpb,
                                                   float* __restrict__ outp) {
    int win = blockIdx.x;
    int head = blockIdx.y;
    __shared__ float q[49][33], k[49][33], v[49][33];
    __shared__ float S[49][50];
    int tid = threadIdx.x;
    const float* base = qkv + (size_t)win * N_ * (3 * C_) + head * 32;
    for (int idx = tid; idx < 49 * 32; idx += 256) {
        int n = idx >> 5, d = idx & 31;
        const float* row = base + (size_t)n * (3 * C_);
        q[n][d] = row[d] * 0.17677669529663689f;   // HD^-0.5
        k[n][d] = row[C_ + d];
        v[n][d] = row[2 * C_ + d];
    }
    __syncthreads();

    int wi = win & 63;
    int wh = wi >> 3, ww = wi & 7;
    for (int p = tid; p < 49 * 49; p += 256) {
        int n = p / 49, m = p % 49;
        float s = 0.0f;
#pragma unroll
        for (int d = 0; d < 32; d++) s += q[n][d] * k[m][d];
        int i1 = n / 7, j1 = n % 7, i2 = m / 7, j2 = m % 7;
        int ridx = (i1 - i2 + 6) * 13 + (j1 - j2 + 6);
        s += rpb[ridx * NH_ + head];
        // shift-window mask (region equality on unshifted image coords)
        int h1 = wh * 7 + i1, w1 = ww * 7 + j1;
        int h2 = wh * 7 + i2, w2 = ww * 7 + j2;
        int r1 = (h1 < 49 ? 0 : (h1 < 53 ? 1 : 2)) * 3 + (w1 < 49 ? 0 : (w1 < 53 ? 1 : 2));
        int r2 = (h2 < 49 ? 0 : (h2 < 53 ? 1 : 2)) * 3 + (w2 < 49 ? 0 : (w2 < 53 ? 1 : 2));
        if (r1 != r2) s -= 100.0f;
        S[n][m] = s;
    }
    __syncthreads();

    if (tid < 49) {
        float mx = -1e30f;
#pragma unroll 7
        for (int m = 0; m < 49; m++) mx = fmaxf(mx, S[tid][m]);
        float sum = 0.0f;
#pragma unroll 7
        for (int m = 0; m < 49; m++) {
            float e = __expf(S[tid][m] - mx);
            S[tid][m] = e;
            sum += e;
        }
        float inv = 1.0f / sum;
#pragma unroll 7
        for (int m = 0; m < 49; m++) S[tid][m] *= inv;
    }
    __syncthreads();

    for (int p = tid; p < 49 * 32; p += 256) {
        int n = p >> 5, d = p & 31;
        float o = 0.0f;
#pragma unroll 7
        for (int m = 0; m < 49; m++) o += S[n][m] * v[m][d];
        outp[((size_t)win * N_ + n) * C_ + head * 32 + d] = o;
    }
}

// ---------------- window-reverse + roll(+3,+3) + residual ----------------
__global__ void winrev_kernel(const float* __restrict__ y, const float* __restrict__ xT,
                              float* __restrict__ xres) {
    int idx = blockIdx.x * blockDim.x + threadIdx.x;
    if (idx >= TOK * (C_ / 4)) return;
    int t = idx / (C_ / 4);
    int c4 = (idx % (C_ / 4)) * 4;
    int bb = t / (H_ * W_), hw = t % (H_ * W_);
    int h = hw / W_, w = hw % W_;
    int h2 = (h + H_ - 3) % H_;   // roll back +3
    int w2 = (w + W_ - 3) % W_;
    int row = (bb * 64 + (h2 / 7) * 8 + (w2 / 7)) * N_ + (h2 % 7) * 7 + (w2 % 7);
    float4 a = *(const float4*)(xT + (size_t)t * C_ + c4);
    float4 yy = *(const float4*)(y + (size_t)row * C_ + c4);
    a.x += yy.x; a.y += yy.y; a.z += yy.z; a.w += yy.w;
    *(float4*)(xres + (size_t)t * C_ + c4) = a;
}

// ---------------- launcher ----------------
extern "C" void kernel_launch(void* const* d_in, const int* in_sizes, int n_in,
                              void* d_out, int out_size) {
    (void)in_sizes; (void)n_in; (void)out_size;
    const float* x      = (const float*)d_in[0];
    const float* qkv_w  = (const float*)d_in[1];
    const float* qkv_b  = (const float*)d_in[2];
    const float* proj_w = (const float*)d_in[3];
    const float* proj_b = (const float*)d_in[4];
    const float* rpb    = (const float*)d_in[5];
    const float* n1w    = (const float*)d_in[6];
    const float* n1b    = (const float*)d_in[7];
    const float* n2w    = (const float*)d_in[8];
    const float* n2b    = (const float*)d_in[9];
    const float* fc1w   = (const float*)d_in[10];
    const float* fc1b   = (const float*)d_in[11];
    const float* fc2w   = (const float*)d_in[12];
    const float* fc2b   = (const float*)d_in[13];
    float* out = (float*)d_out;

    float *xT, *a, *attn, *res, *big;
    cudaGetSymbolAddress((void**)&xT,   g_xT);
    cudaGetSymbolAddress((void**)&a,    g_a);
    cudaGetSymbolAddress((void**)&attn, g_attn);
    cudaGetSymbolAddress((void**)&res,  g_res);
    cudaGetSymbolAddress((void**)&big,  g_big);

    // 1. (B,C,H,W) -> (B,H,W,C)
    transpose_kernel<<<dim3(98, 12, 32), dim3(32, 8)>>>(x, xT, C_, H_ * W_);
    // 2. shift + window partition + LN1
    ln_win_kernel<<<TOK, 128>>>(xT, n1w, n1b, a);
    // 3. QKV GEMM (tok x 1152)
    gemm_kernel<<<dim3(TOK / 64, (3 * C_) / 64), 256>>>(a, qkv_w, qkv_b, big, nullptr,
                                                        TOK, 3 * C_, C_, 0);
    // 4. fused window attention
    attn_kernel<<<dim3(WINS, NH_), 256>>>(big, rpb, attn);
    // 5. proj GEMM
    gemm_kernel<<<dim3(TOK / 64, C_ / 64), 256>>>(attn, proj_w, proj_b, a, nullptr,
                                                  TOK, C_, C_, 0);
    // 6. window reverse + roll back + residual
    winrev_kernel<<<(TOK * (C_ / 4) + 255) / 256, 256>>>(a, xT, res);
    // 7. LN2
    ln_plain_kernel<<<TOK, 128>>>(res, n2w, n2b, a);
    // 8. FC1 GEMM + GELU
    gemm_kernel<<<dim3(TOK / 64, HID_ / 64), 256>>>(a, fc1w, fc1b, big, nullptr,
                                                    TOK, HID_, C_, 1);
    // 9. FC2 GEMM + residual
    gemm_kernel<<<dim3(TOK / 64, C_ / 64), 256>>>(big, fc2w, fc2b, attn, res,
                                                  TOK, C_, HID_, 2);
    // 10. (B,H,W,C) -> (B,C,H,W)
    transpose_kernel<<<dim3(12, 98, 32), dim3(32, 8)>>>(attn, out, H_ * W_, C_);
}

// round 5
// speedup vs baseline: 6.0967x; 6.0967x over previous
#include <cuda_runtime.h>
#include <cstdint>

// ---------------- constants ----------------
namespace {
constexpr int B_  = 32;
constexpr int C_  = 384;
constexpr int H_  = 56;
constexpr int W_  = 56;
constexpr int WS_ = 7;
constexpr int NH_ = 12;
constexpr int N_  = 49;     // WS*WS
constexpr int TOK = B_ * H_ * W_;    // 100352
constexpr int HID_ = 4 * C_;         // 1536
constexpr int WINS = TOK / N_;       // 2048
}

// ---------------- scratch (device globals; no runtime allocation) ----------------
__device__ float g_xT[TOK * C_];     // x in (B,H,W,C) layout (shortcut)
__device__ float g_a[TOK * C_];      // xw_ln -> proj_out -> xn (reused)
__device__ float g_attn[TOK * C_];   // attention out -> final pre-transpose (reused)
__device__ float g_res[TOK * C_];    // residual after attention branch
__device__ float g_big[TOK * HID_];  // qkv (tok x 1152) then mlp hidden (tok x 1536)

// ---------------- tf32 helper ----------------
__device__ __forceinline__ float f2tf32(float x) {
    uint32_t r;
    asm("cvt.rna.tf32.f32 %0, %1;" : "=r"(r) : "f"(x));
    return __uint_as_float(r);
}

// ---------------- tiled batch transpose: dst[b][col][row] = src[b][row][col] ----------------
__global__ void transpose_kernel(const float* __restrict__ src, float* __restrict__ dst,
                                 int rows, int cols) {
    __shared__ float t[32][33];
    int b = blockIdx.z;
    const float* s = src + (size_t)b * rows * cols;
    float* d = dst + (size_t)b * rows * cols;
    int c0 = blockIdx.x * 32, r0 = blockIdx.y * 32;
    int tx = threadIdx.x, ty = threadIdx.y;
#pragma unroll
    for (int i = 0; i < 32; i += 8)
        t[ty + i][tx] = s[(size_t)(r0 + ty + i) * cols + c0 + tx];
    __syncthreads();
#pragma unroll
    for (int i = 0; i < 32; i += 8)
        d[(size_t)(c0 + ty + i) * rows + r0 + tx] = t[tx][ty + i];
}

// ---------------- LayerNorm helpers ----------------
__device__ __forceinline__ void block_ln_stats_128(float x0, float x1, float x2,
                                                   float& mean, float& rstd) {
    __shared__ float red[8];
    float s = x0 + x1 + x2;
    float s2 = x0 * x0 + x1 * x1 + x2 * x2;
#pragma unroll
    for (int o = 16; o > 0; o >>= 1) {
        s  += __shfl_xor_sync(0xffffffffu, s, o);
        s2 += __shfl_xor_sync(0xffffffffu, s2, o);
    }
    int w = threadIdx.x >> 5;
    if ((threadIdx.x & 31) == 0) { red[w] = s; red[4 + w] = s2; }
    __syncthreads();
    s  = red[0] + red[1] + red[2] + red[3];
    s2 = red[4] + red[5] + red[6] + red[7];
    mean = s * (1.0f / 384.0f);
    float var = s2 * (1.0f / 384.0f) - mean * mean;
    rstd = rsqrtf(var + 1e-5f);
}

// shift (-3,-3) + window-partition + LN1: out row r = (win, n) order
__global__ __launch_bounds__(128) void ln_win_kernel(const float* __restrict__ xT,
                                                     const float* __restrict__ g,
                                                     const float* __restrict__ b,
                                                     float* __restrict__ out) {
    int r = blockIdx.x;
    int win = r / N_, n = r % N_;
    int bb = win >> 6, wi = win & 63;
    int wh = wi >> 3, ww = wi & 7;
    int i = n / WS_, j = n % WS_;
    int hs = (wh * WS_ + i + 3) % H_;
    int ws = (ww * WS_ + j + 3) % W_;
    const float* src = xT + ((size_t)(bb * H_ + hs) * W_ + ws) * C_;
    int t = threadIdx.x;
    float x0 = src[t], x1 = src[t + 128], x2 = src[t + 256];
    float mean, rstd;
    block_ln_stats_128(x0, x1, x2, mean, rstd);
    float* o = out + (size_t)r * C_;
    o[t]       = (x0 - mean) * rstd * g[t]       + b[t];
    o[t + 128] = (x1 - mean) * rstd * g[t + 128] + b[t + 128];
    o[t + 256] = (x2 - mean) * rstd * g[t + 256] + b[t + 256];
}

// plain LN over rows (token natural order)
__global__ __launch_bounds__(128) void ln_plain_kernel(const float* __restrict__ in,
                                                       const float* __restrict__ g,
                                                       const float* __restrict__ b,
                                                       float* __restrict__ out) {
    int r = blockIdx.x;
    const float* src = in + (size_t)r * C_;
    int t = threadIdx.x;
    float x0 = src[t], x1 = src[t + 128], x2 = src[t + 256];
    float mean, rstd;
    block_ln_stats_128(x0, x1, x2, mean, rstd);
    float* o = out + (size_t)r * C_;
    o[t]       = (x0 - mean) * rstd * g[t]       + b[t];
    o[t + 128] = (x1 - mean) * rstd * g[t + 128] + b[t + 128];
    o[t + 256] = (x2 - mean) * rstd * g[t + 256] + b[t + 256];
}

// ---------------- TF32 tensor-core GEMM ----------------
// C[M,N] = A[M,K] @ B[K,N] + bias, epilogue: 0=bias, 1=bias+GELU, 2=bias+residual
// Requires M%128==0, N%128==0, K%16==0.
// Block tile 128x128x16, 256 threads = 8 warps (4 m x 2 n), warp tile 32x64.
// mma.sync.aligned.m16n8k8 tf32, double-buffered smem.
__global__ __launch_bounds__(256) void gemm_tc(const float* __restrict__ A,
                                               const float* __restrict__ Bw,
                                               const float* __restrict__ bias,
                                               float* __restrict__ Cm,
                                               const float* __restrict__ resid,
                                               int M, int Nn, int K, int epi) {
    // A tile stored [m][k] with row stride 20 (g*20+t distinct mod 32 -> conflict-free frag LDS)
    // B tile stored [k][n] with row stride 136 (t*8+g distinct mod 32 -> conflict-free)
    __shared__ __align__(16) float As[2][128][20];
    __shared__ __align__(16) float Bs[2][16][136];

    int tid  = threadIdx.x;
    int lane = tid & 31, warp = tid >> 5;
    int g = lane >> 2, t = lane & 3;
    int wm = (warp & 3) * 32;
    int wn = (warp >> 2) * 64;
    int m0 = blockIdx.x * 128, n0 = blockIdx.y * 128;

    // gmem load indices: A tile = 128 rows x 4 float4; B tile = 16 rows x 32 float4
    int arA = tid >> 2;            // 0..63 (second: +64)
    int acA = (tid & 3) * 4;       // 0,4,8,12
    int brB = tid >> 5;            // 0..7 (second: +8)
    int bcB = (tid & 31) * 4;      // 0..124

    float c[2][8][4];
#pragma unroll
    for (int i = 0; i < 2; i++)
#pragma unroll
        for (int j = 0; j < 8; j++)
#pragma unroll
            for (int q = 0; q < 4; q++) c[i][j][q] = 0.0f;

    const int nIter = K >> 4;
    float4 pA0, pA1, pB0, pB1;

    // prologue: load k-tile 0, convert to tf32, store into buf 0
    pA0 = *(const float4*)(A + (size_t)(m0 + arA)      * K + acA);
    pA1 = *(const float4*)(A + (size_t)(m0 + arA + 64) * K + acA);
    pB0 = *(const float4*)(Bw + (size_t)(brB)     * Nn + n0 + bcB);
    pB1 = *(const float4*)(Bw + (size_t)(brB + 8) * Nn + n0 + bcB);
    {
        float* a0 = &As[0][arA][acA];
        a0[0] = f2tf32(pA0.x); a0[1] = f2tf32(pA0.y); a0[2] = f2tf32(pA0.z); a0[3] = f2tf32(pA0.w);
        float* a1 = &As[0][arA + 64][acA];
        a1[0] = f2tf32(pA1.x); a1[1] = f2tf32(pA1.y); a1[2] = f2tf32(pA1.z); a1[3] = f2tf32(pA1.w);
        float* b0 = &Bs[0][brB][bcB];
        b0[0] = f2tf32(pB0.x); b0[1] = f2tf32(pB0.y); b0[2] = f2tf32(pB0.z); b0[3] = f2tf32(pB0.w);
        float* b1 = &Bs[0][brB + 8][bcB];
        b1[0] = f2tf32(pB1.x); b1[1] = f2tf32(pB1.y); b1[2] = f2tf32(pB1.z); b1[3] = f2tf32(pB1.w);
    }
    __syncthreads();

    for (int it = 0; it < nIter; ++it) {
        int buf = it & 1;
        bool more = (it + 1) < nIter;
        if (more) {
            int k0 = (it + 1) << 4;
            pA0 = *(const float4*)(A + (size_t)(m0 + arA)      * K + k0 + acA);
            pA1 = *(const float4*)(A + (size_t)(m0 + arA + 64) * K + k0 + acA);
            pB0 = *(const float4*)(Bw + (size_t)(k0 + brB)     * Nn + n0 + bcB);
            pB1 = *(const float4*)(Bw + (size_t)(k0 + brB + 8) * Nn + n0 + bcB);
        }
#pragma unroll
        for (int kk = 0; kk < 16; kk += 8) {
            uint32_t af[2][4];
#pragma unroll
            for (int i = 0; i < 2; i++) {
                af[i][0] = __float_as_uint(As[buf][wm + 16 * i + g][kk + t]);
                af[i][1] = __float_as_uint(As[buf][wm + 16 * i + g + 8][kk + t]);
                af[i][2] = __float_as_uint(As[buf][wm + 16 * i + g][kk + t + 4]);
                af[i][3] = __float_as_uint(As[buf][wm + 16 * i + g + 8][kk + t + 4]);
            }
            uint32_t bf[8][2];
#pragma unroll
            for (int j = 0; j < 8; j++) {
                bf[j][0] = __float_as_uint(Bs[buf][kk + t][wn + 8 * j + g]);
                bf[j][1] = __float_as_uint(Bs[buf][kk + t + 4][wn + 8 * j + g]);
            }
#pragma unroll
            for (int i = 0; i < 2; i++)
#pragma unroll
                for (int j = 0; j < 8; j++)
                    asm volatile(
                        "mma.sync.aligned.m16n8k8.row.col.f32.tf32.tf32.f32 "
                        "{%0,%1,%2,%3}, {%4,%5,%6,%7}, {%8,%9}, {%0,%1,%2,%3};"
                        : "+f"(c[i][j][0]), "+f"(c[i][j][1]),
                          "+f"(c[i][j][2]), "+f"(c[i][j][3])
                        : "r"(af[i][0]), "r"(af[i][1]), "r"(af[i][2]), "r"(af[i][3]),
                          "r"(bf[j][0]), "r"(bf[j][1]));
        }
        if (more) {
            int nb = buf ^ 1;
            float* a0 = &As[nb][arA][acA];
            a0[0] = f2tf32(pA0.x); a0[1] = f2tf32(pA0.y); a0[2] = f2tf32(pA0.z); a0[3] = f2tf32(pA0.w);
            float* a1 = &As[nb][arA + 64][acA];
            a1[0] = f2tf32(pA1.x); a1[1] = f2tf32(pA1.y); a1[2] = f2tf32(pA1.z); a1[3] = f2tf32(pA1.w);
            float* b0 = &Bs[nb][brB][bcB];
            b0[0] = f2tf32(pB0.x); b0[1] = f2tf32(pB0.y); b0[2] = f2tf32(pB0.z); b0[3] = f2tf32(pB0.w);
            float* b1 = &Bs[nb][brB + 8][bcB];
            b1[0] = f2tf32(pB1.x); b1[1] = f2tf32(pB1.y); b1[2] = f2tf32(pB1.z); b1[3] = f2tf32(pB1.w);
            __syncthreads();
        }
    }

    // epilogue
#pragma unroll
    for (int i = 0; i < 2; i++) {
        int rA = m0 + wm + 16 * i + g;
#pragma unroll
        for (int j = 0; j < 8; j++) {
            int col = n0 + wn + 8 * j + 2 * t;
            float b0 = bias[col], b1 = bias[col + 1];
            float v0 = c[i][j][0] + b0;
            float v1 = c[i][j][1] + b1;
            float v2 = c[i][j][2] + b0;
            float v3 = c[i][j][3] + b1;
            if (epi == 1) {
                v0 = 0.5f * v0 * (1.0f + erff(v0 * 0.70710678118654752f));
                v1 = 0.5f * v1 * (1.0f + erff(v1 * 0.70710678118654752f));
                v2 = 0.5f * v2 * (1.0f + erff(v2 * 0.70710678118654752f));
                v3 = 0.5f * v3 * (1.0f + erff(v3 * 0.70710678118654752f));
            } else if (epi == 2) {
                float2 r0 = *(const float2*)(resid + (size_t)rA * Nn + col);
                float2 r1 = *(const float2*)(resid + (size_t)(rA + 8) * Nn + col);
                v0 += r0.x; v1 += r0.y; v2 += r1.x; v3 += r1.y;
            }
            *(float2*)(Cm + (size_t)rA * Nn + col)       = make_float2(v0, v1);
            *(float2*)(Cm + (size_t)(rA + 8) * Nn + col) = make_float2(v2, v3);
        }
    }
}

// ---------------- fused window attention: one block per (window, head) ----------------
__global__ __launch_bounds__(256) void attn_kernel(const float* __restrict__ qkv,
                                                   const float* __restrict__ rpb,
                                                   float* __restrict__ outp) {
    int win = blockIdx.x;
    int head = blockIdx.y;
    __shared__ float q[49][33], k[49][33], v[49][33];
    __shared__ float S[49][50];
    int tid = threadIdx.x;
    const float* base = qkv + (size_t)win * N_ * (3 * C_) + head * 32;
    for (int idx = tid; idx < 49 * 32; idx += 256) {
        int n = idx >> 5, d = idx & 31;
        const float* row = base + (size_t)n * (3 * C_);
        q[n][d] = row[d] * 0.17677669529663689f;
        k[n][d] = row[C_ + d];
        v[n][d] = row[2 * C_ + d];
    }
    __syncthreads();

    int wi = win & 63;
    int wh = wi >> 3, ww = wi & 7;
    for (int p = tid; p < 49 * 49; p += 256) {
        int n = p / 49, m = p % 49;
        float s = 0.0f;
#pragma unroll
        for (int d = 0; d < 32; d++) s += q[n][d] * k[m][d];
        int i1 = n / 7, j1 = n % 7, i2 = m / 7, j2 = m % 7;
        int ridx = (i1 - i2 + 6) * 13 + (j1 - j2 + 6);
        s += rpb[ridx * NH_ + head];
        int h1 = wh * 7 + i1, w1 = ww * 7 + j1;
        int h2 = wh * 7 + i2, w2 = ww * 7 + j2;
        int r1 = (h1 < 49 ? 0 : (h1 < 53 ? 1 : 2)) * 3 + (w1 < 49 ? 0 : (w1 < 53 ? 1 : 2));
        int r2 = (h2 < 49 ? 0 : (h2 < 53 ? 1 : 2)) * 3 + (w2 < 49 ? 0 : (w2 < 53 ? 1 : 2));
        if (r1 != r2) s -= 100.0f;
        S[n][m] = s;
    }
    __syncthreads();

    if (tid < 49) {
        float mx = -1e30f;
#pragma unroll 7
        for (int m = 0; m < 49; m++) mx = fmaxf(mx, S[tid][m]);
        float sum = 0.0f;
#pragma unroll 7
        for (int m = 0; m < 49; m++) {
            float e = __expf(S[tid][m] - mx);
            S[tid][m] = e;
            sum += e;
        }
        float inv = 1.0f / sum;
#pragma unroll 7
        for (int m = 0; m < 49; m++) S[tid][m] *= inv;
    }
    __syncthreads();

    for (int p = tid; p < 49 * 32; p += 256) {
        int n = p >> 5, d = p & 31;
        float o = 0.0f;
#pragma unroll 7
        for (int m = 0; m < 49; m++) o += S[n][m] * v[m][d];
        outp[((size_t)win * N_ + n) * C_ + head * 32 + d] = o;
    }
}

// ---------------- window-reverse + roll(+3,+3) + residual ----------------
__global__ void winrev_kernel(const float* __restrict__ y, const float* __restrict__ xT,
                              float* __restrict__ xres) {
    int idx = blockIdx.x * blockDim.x + threadIdx.x;
    if (idx >= TOK * (C_ / 4)) return;
    int t = idx / (C_ / 4);
    int c4 = (idx % (C_ / 4)) * 4;
    int bb = t / (H_ * W_), hw = t % (H_ * W_);
    int h = hw / W_, w = hw % W_;
    int h2 = (h + H_ - 3) % H_;
    int w2 = (w + W_ - 3) % W_;
    int row = (bb * 64 + (h2 / 7) * 8 + (w2 / 7)) * N_ + (h2 % 7) * 7 + (w2 % 7);
    float4 a = *(const float4*)(xT + (size_t)t * C_ + c4);
    float4 yy = *(const float4*)(y + (size_t)row * C_ + c4);
    a.x += yy.x; a.y += yy.y; a.z += yy.z; a.w += yy.w;
    *(float4*)(xres + (size_t)t * C_ + c4) = a;
}

// ---------------- launcher ----------------
extern "C" void kernel_launch(void* const* d_in, const int* in_sizes, int n_in,
                              void* d_out, int out_size) {
    (void)in_sizes; (void)n_in; (void)out_size;
    const float* x      = (const float*)d_in[0];
    const float* qkv_w  = (const float*)d_in[1];
    const float* qkv_b  = (const float*)d_in[2];
    const float* proj_w = (const float*)d_in[3];
    const float* proj_b = (const float*)d_in[4];
    const float* rpb    = (const float*)d_in[5];
    const float* n1w    = (const float*)d_in[6];
    const float* n1b    = (const float*)d_in[7];
    const float* n2w    = (const float*)d_in[8];
    const float* n2b    = (const float*)d_in[9];
    const float* fc1w   = (const float*)d_in[10];
    const float* fc1b   = (const float*)d_in[11];
    const float* fc2w   = (const float*)d_in[12];
    const float* fc2b   = (const float*)d_in[13];
    float* out = (float*)d_out;

    float *xT, *a, *attn, *res, *big;
    cudaGetSymbolAddress((void**)&xT,   g_xT);
    cudaGetSymbolAddress((void**)&a,    g_a);
    cudaGetSymbolAddress((void**)&attn, g_attn);
    cudaGetSymbolAddress((void**)&res,  g_res);
    cudaGetSymbolAddress((void**)&big,  g_big);

    // 1. (B,C,H,W) -> (B,H,W,C)
    transpose_kernel<<<dim3(98, 12, 32), dim3(32, 8)>>>(x, xT, C_, H_ * W_);
    // 2. shift + window partition + LN1
    ln_win_kernel<<<TOK, 128>>>(xT, n1w, n1b, a);
    // 3. QKV GEMM (tok x 1152)
    gemm_tc<<<dim3(TOK / 128, (3 * C_) / 128), 256>>>(a, qkv_w, qkv_b, big, nullptr,
                                                      TOK, 3 * C_, C_, 0);
    // 4. fused window attention
    attn_kernel<<<dim3(WINS, NH_), 256>>>(big, rpb, attn);
    // 5. proj GEMM
    gemm_tc<<<dim3(TOK / 128, C_ / 128), 256>>>(attn, proj_w, proj_b, a, nullptr,
                                                TOK, C_, C_, 0);
    // 6. window reverse + roll back + residual
    winrev_kernel<<<(TOK * (C_ / 4) + 255) / 256, 256>>>(a, xT, res);
    // 7. LN2
    ln_plain_kernel<<<TOK, 128>>>(res, n2w, n2b, a);
    // 8. FC1 GEMM + GELU
    gemm_tc<<<dim3(TOK / 128, HID_ / 128), 256>>>(a, fc1w, fc1b, big, nullptr,
                                                  TOK, HID_, C_, 1);
    // 9. FC2 GEMM + residual
    gemm_tc<<<dim3(TOK / 128, C_ / 128), 256>>>(big, fc2w, fc2b, attn, res,
                                                TOK, C_, HID_, 2);
    // 10. (B,H,W,C) -> (B,C,H,W)
    transpose_kernel<<<dim3(12, 98, 32), dim3(32, 8)>>>(attn, out, H_ * W_, C_);
}

// round 12
// speedup vs baseline: 8.0998x; 1.3286x over previous
#include <cuda_runtime.h>
#include <cuda_fp16.h>
#include <cstdint>

// ---------------- constants ----------------
namespace {
constexpr int B_  = 32;
constexpr int C_  = 384;
constexpr int H_  = 56;
constexpr int W_  = 56;
constexpr int WS_ = 7;
constexpr int NH_ = 12;
constexpr int N_  = 49;
constexpr int TOK = B_ * H_ * W_;    // 100352
constexpr int HID_ = 4 * C_;         // 1536
constexpr int WINS = TOK / N_;       // 2048

// weight-transpose scratch offsets (half elements)
constexpr int QKVT_OFF = 0;
constexpr int PROJT_OFF = 442368;            // 1152*384
constexpr int FC1T_OFF = 589824;             // + 384*384
constexpr int FC2T_OFF = 1179648;            // + 1536*384
}

// ---------------- scratch (device globals; no runtime allocation) ----------------
__device__ float  g_xT[TOK * C_];        // x in (B,H,W,C) layout (shortcut)
__device__ float  g_a[TOK * C_];         // proj out (f32)
__device__ float  g_attn[TOK * C_];      // final pre-transpose (f32)
__device__ float  g_res[TOK * C_];       // residual after attention branch
__device__ float  g_big[TOK * 3 * C_];   // qkv out (f32)
__device__ __half g_h1[TOK * C_];        // half A-operand: ln1 out / attn out / ln2 out
__device__ __half g_h2[TOK * HID_];      // half A-operand: fc1+gelu out
__device__ __half g_wT[1769472];         // all transposed weights (half, [N][K])

// ---------------- tiled batch transpose ----------------
__global__ void transpose_kernel(const float* __restrict__ src, float* __restrict__ dst,
                                 int rows, int cols) {
    __shared__ float t[32][33];
    int b = blockIdx.z;
    const float* s = src + (size_t)b * rows * cols;
    float* d = dst + (size_t)b * rows * cols;
    int c0 = blockIdx.x * 32, r0 = blockIdx.y * 32;
    int tx = threadIdx.x, ty = threadIdx.y;
#pragma unroll
    for (int i = 0; i < 32; i += 8)
        t[ty + i][tx] = s[(size_t)(r0 + ty + i) * cols + c0 + tx];
    __syncthreads();
#pragma unroll
    for (int i = 0; i < 32; i += 8)
        d[(size_t)(c0 + ty + i) * rows + r0 + tx] = t[tx][ty + i];
}

// weight transpose + fp16 rounding: src[K][N] f32 -> dst[N][K] half
__global__ void wtrans_kernel(const float* __restrict__ src, __half* __restrict__ dst,
                              int K, int N) {
    __shared__ float t[32][33];
    int n0 = blockIdx.x * 32, k0 = blockIdx.y * 32;
    int tx = threadIdx.x, ty = threadIdx.y;
#pragma unroll
    for (int i = 0; i < 32; i += 8)
        t[ty + i][tx] = src[(size_t)(k0 + ty + i) * N + n0 + tx];
    __syncthreads();
#pragma unroll
    for (int i = 0; i < 32; i += 8)
        dst[(size_t)(n0 + ty + i) * K + k0 + tx] = __float2half_rn(t[tx][ty + i]);
}

// ---------------- LayerNorm ----------------
__device__ __forceinline__ void block_ln_stats_128(float x0, float x1, float x2,
                                                   float& mean, float& rstd) {
    __shared__ float red[8];
    float s = x0 + x1 + x2;
    float s2 = x0 * x0 + x1 * x1 + x2 * x2;
#pragma unroll
    for (int o = 16; o > 0; o >>= 1) {
        s  += __shfl_xor_sync(0xffffffffu, s, o);
        s2 += __shfl_xor_sync(0xffffffffu, s2, o);
    }
    int w = threadIdx.x >> 5;
    if ((threadIdx.x & 31) == 0) { red[w] = s; red[4 + w] = s2; }
    __syncthreads();
    s  = red[0] + red[1] + red[2] + red[3];
    s2 = red[4] + red[5] + red[6] + red[7];
    mean = s * (1.0f / 384.0f);
    float var = s2 * (1.0f / 384.0f) - mean * mean;
    rstd = rsqrtf(var + 1e-5f);
}

// shift + window partition + LN1 -> half (feeds QKV GEMM)
__global__ __launch_bounds__(128) void ln_win_kernel(const float* __restrict__ xT,
                                                     const float* __restrict__ g,
                                                     const float* __restrict__ b,
                                                     __half* __restrict__ out) {
    int r = blockIdx.x;
    int win = r / N_, n = r % N_;
    int bb = win >> 6, wi = win & 63;
    int wh = wi >> 3, ww = wi & 7;
    int i = n / WS_, j = n % WS_;
    int hs = (wh * WS_ + i + 3) % H_;
    int ws = (ww * WS_ + j + 3) % W_;
    const float* src = xT + ((size_t)(bb * H_ + hs) * W_ + ws) * C_;
    int t = threadIdx.x;
    float x0 = src[t], x1 = src[t + 128], x2 = src[t + 256];
    float mean, rstd;
    block_ln_stats_128(x0, x1, x2, mean, rstd);
    __half* o = out + (size_t)r * C_;
    o[t]       = __float2half_rn((x0 - mean) * rstd * g[t]       + b[t]);
    o[t + 128] = __float2half_rn((x1 - mean) * rstd * g[t + 128] + b[t + 128]);
    o[t + 256] = __float2half_rn((x2 - mean) * rstd * g[t + 256] + b[t + 256]);
}

// plain LN -> half (feeds FC1 GEMM)
__global__ __launch_bounds__(128) void ln_plain_kernel(const float* __restrict__ in,
                                                       const float* __restrict__ g,
                                                       const float* __restrict__ b,
                                                       __half* __restrict__ out) {
    int r = blockIdx.x;
    const float* src = in + (size_t)r * C_;
    int t = threadIdx.x;
    float x0 = src[t], x1 = src[t + 128], x2 = src[t + 256];
    float mean, rstd;
    block_ln_stats_128(x0, x1, x2, mean, rstd);
    __half* o = out + (size_t)r * C_;
    o[t]       = __float2half_rn((x0 - mean) * rstd * g[t]       + b[t]);
    o[t + 128] = __float2half_rn((x1 - mean) * rstd * g[t + 128] + b[t + 128]);
    o[t + 256] = __float2half_rn((x2 - mean) * rstd * g[t + 256] + b[t + 256]);
}

// ---------------- FP16 tensor-core GEMM (mma.sync.m16n8k16, f32 accum) ----------------
// C[M,Nn] = A[M,K] @ Bt[Nn,K]^T + bias
// epi: 0 = bias -> f32 out; 1 = bias + exact GELU -> half out; 2 = bias + resid -> f32 out
// M%128==0, Nn%128==0, K%32==0. A, Bt are half.
// Block tile 128x128x32, 256 threads = 8 warps (4 m x 2 n), warp tile 32x64.
__global__ __launch_bounds__(256) void gemm_h(const __half* __restrict__ A,
                                              const __half* __restrict__ Bt,
                                              const float* __restrict__ bias,
                                              void* __restrict__ Cm,
                                              const float* __restrict__ resid,
                                              int M, int Nn, int K, int epi) {
    // [row][k] layout, row stride 40 halves: fragment LDS.32 banks (20g+t) mod 32 distinct
    __shared__ __align__(16) __half As[2][128][40];
    __shared__ __align__(16) __half Bs[2][128][40];

    int tid  = threadIdx.x;
    int lane = tid & 31, warp = tid >> 5;
    int g = lane >> 2, t = lane & 3;
    int wm = (warp & 3) * 32;
    int wn = (warp >> 2) * 64;
    int m0 = blockIdx.x * 128, n0 = blockIdx.y * 128;

    int lr = tid >> 1;           // 0..127 tile row
    int lc = (tid & 1) * 16;     // 0 or 16 (half index within 32-wide k tile)
    const __half* gA = A  + (size_t)(m0 + lr) * K + lc;
    const __half* gB = Bt + (size_t)(n0 + lr) * K + lc;

    float c[2][8][4];
#pragma unroll
    for (int i = 0; i < 2; i++)
#pragma unroll
        for (int j = 0; j < 8; j++)
#pragma unroll
            for (int q = 0; q < 4; q++) c[i][j][q] = 0.0f;

    const int nIter = K >> 5;
    uint4 pa0, pa1, pb0, pb1;

    // prologue: tile 0 -> buf 0
    pa0 = *(const uint4*)(gA);
    pa1 = *(const uint4*)(gA + 8);
    pb0 = *(const uint4*)(gB);
    pb1 = *(const uint4*)(gB + 8);
    *(uint4*)&As[0][lr][lc]     = pa0;
    *(uint4*)&As[0][lr][lc + 8] = pa1;
    *(uint4*)&Bs[0][lr][lc]     = pb0;
    *(uint4*)&Bs[0][lr][lc + 8] = pb1;
    __syncthreads();

    for (int it = 0; it < nIter; ++it) {
        int buf = it & 1;
        bool more = (it + 1) < nIter;
        if (more) {
            const __half* ga = gA + (size_t)(it + 1) * 32;
            const __half* gb = gB + (size_t)(it + 1) * 32;
            pa0 = *(const uint4*)(ga);
            pa1 = *(const uint4*)(ga + 8);
            pb0 = *(const uint4*)(gb);
            pb1 = *(const uint4*)(gb + 8);
        }
#pragma unroll
        for (int ks = 0; ks < 32; ks += 16) {
            uint32_t af[2][4];
#pragma unroll
            for (int i = 0; i < 2; i++) {
                af[i][0] = *(const uint32_t*)&As[buf][wm + 16 * i + g][ks + 2 * t];
                af[i][1] = *(const uint32_t*)&As[buf][wm + 16 * i + g + 8][ks + 2 * t];
                af[i][2] = *(const uint32_t*)&As[buf][wm + 16 * i + g][ks + 2 * t + 8];
                af[i][3] = *(const uint32_t*)&As[buf][wm + 16 * i + g + 8][ks + 2 * t + 8];
            }
            uint32_t bf[8][2];
#pragma unroll
            for (int j = 0; j < 8; j++) {
                bf[j][0] = *(const uint32_t*)&Bs[buf][wn + 8 * j + g][ks + 2 * t];
                bf[j][1] = *(const uint32_t*)&Bs[buf][wn + 8 * j + g][ks + 2 * t + 8];
            }
#pragma unroll
            for (int i = 0; i < 2; i++)
#pragma unroll
                for (int j = 0; j < 8; j++)
                    asm volatile(
                        "mma.sync.aligned.m16n8k16.row.col.f32.f16.f16.f32 "
                        "{%0,%1,%2,%3}, {%4,%5,%6,%7}, {%8,%9}, {%0,%1,%2,%3};"
                        : "+f"(c[i][j][0]), "+f"(c[i][j][1]),
                          "+f"(c[i][j][2]), "+f"(c[i][j][3])
                        : "r"(af[i][0]), "r"(af[i][1]), "r"(af[i][2]), "r"(af[i][3]),
                          "r"(bf[j][0]), "r"(bf[j][1]));
        }
        if (more) {
            int nb = buf ^ 1;
            *(uint4*)&As[nb][lr][lc]     = pa0;
            *(uint4*)&As[nb][lr][lc + 8] = pa1;
            *(uint4*)&Bs[nb][lr][lc]     = pb0;
            *(uint4*)&Bs[nb][lr][lc + 8] = pb1;
            __syncthreads();
        }
    }

    // epilogue
    float* Cf = (float*)Cm;
    __half* Ch = (__half*)Cm;
#pragma unroll
    for (int i = 0; i < 2; i++) {
        int rA = m0 + wm + 16 * i + g;
#pragma unroll
        for (int j = 0; j < 8; j++) {
            int col = n0 + wn + 8 * j + 2 * t;
            float b0 = bias[col], b1 = bias[col + 1];
            float v0 = c[i][j][0] + b0;
            float v1 = c[i][j][1] + b1;
            float v2 = c[i][j][2] + b0;
            float v3 = c[i][j][3] + b1;
            if (epi == 1) {
                v0 = 0.5f * v0 * (1.0f + erff(v0 * 0.70710678118654752f));
                v1 = 0.5f * v1 * (1.0f + erff(v1 * 0.70710678118654752f));
                v2 = 0.5f * v2 * (1.0f + erff(v2 * 0.70710678118654752f));
                v3 = 0.5f * v3 * (1.0f + erff(v3 * 0.70710678118654752f));
                *(__half2*)(Ch + (size_t)rA * Nn + col) =
                    __floats2half2_rn(v0, v1);
                *(__half2*)(Ch + (size_t)(rA + 8) * Nn + col) =
                    __floats2half2_rn(v2, v3);
            } else {
                if (epi == 2) {
                    float2 r0 = *(const float2*)(resid + (size_t)rA * Nn + col);
                    float2 r1 = *(const float2*)(resid + (size_t)(rA + 8) * Nn + col);
                    v0 += r0.x; v1 += r0.y; v2 += r1.x; v3 += r1.y;
                }
                *(float2*)(Cf + (size_t)rA * Nn + col)       = make_float2(v0, v1);
                *(float2*)(Cf + (size_t)(rA + 8) * Nn + col) = make_float2(v2, v3);
            }
        }
    }
}

// ---------------- fused window attention (fp32 math; half output for proj GEMM) ------
__global__ __launch_bounds__(256) void attn_kernel(const float* __restrict__ qkv,
                                                   const float* __restrict__ rpb,
                                                   __half* __restrict__ outp) {
    int win = blockIdx.x;
    int head = blockIdx.y;
    __shared__ float q[49][33], k[49][33], v[49][33];
    __shared__ float S[49][50];
    int tid = threadIdx.x;
    const float* base = qkv + (size_t)win * N_ * (3 * C_) + head * 32;
    for (int idx = tid; idx < 49 * 32; idx += 256) {
        int n = idx >> 5, d = idx & 31;
        const float* row = base + (size_t)n * (3 * C_);
        q[n][d] = row[d] * 0.17677669529663689f;
        k[n][d] = row[C_ + d];
        v[n][d] = row[2 * C_ + d];
    }
    __syncthreads();

    int wi = win & 63;
    int wh = wi >> 3, ww = wi & 7;
    for (int p = tid; p < 49 * 49; p += 256) {
        int n = p / 49, m = p % 49;
        float s = 0.0f;
#pragma unroll
        for (int d = 0; d < 32; d++) s += q[n][d] * k[m][d];
        int i1 = n / 7, j1 = n % 7, i2 = m / 7, j2 = m % 7;
        int ridx = (i1 - i2 + 6) * 13 + (j1 - j2 + 6);
        s += rpb[ridx * NH_ + head];
        int h1 = wh * 7 + i1, w1 = ww * 7 + j1;
        int h2 = wh * 7 + i2, w2 = ww * 7 + j2;
        int r1 = (h1 < 49 ? 0 : (h1 < 53 ? 1 : 2)) * 3 + (w1 < 49 ? 0 : (w1 < 53 ? 1 : 2));
        int r2 = (h2 < 49 ? 0 : (h2 < 53 ? 1 : 2)) * 3 + (w2 < 49 ? 0 : (w2 < 53 ? 1 : 2));
        if (r1 != r2) s -= 100.0f;
        S[n][m] = s;
    }
    __syncthreads();

    if (tid < 49) {
        float mx = -1e30f;
#pragma unroll 7
        for (int m = 0; m < 49; m++) mx = fmaxf(mx, S[tid][m]);
        float sum = 0.0f;
#pragma unroll 7
        for (int m = 0; m < 49; m++) {
            float e = __expf(S[tid][m] - mx);
            S[tid][m] = e;
            sum += e;
        }
        float inv = 1.0f / sum;
#pragma unroll 7
        for (int m = 0; m < 49; m++) S[tid][m] *= inv;
    }
    __syncthreads();

    for (int p = tid; p < 49 * 32; p += 256) {
        int n = p >> 5, d = p & 31;
        float o = 0.0f;
#pragma unroll 7
        for (int m = 0; m < 49; m++) o += S[n][m] * v[m][d];
        outp[((size_t)win * N_ + n) * C_ + head * 32 + d] = __float2half_rn(o);
    }
}

// ---------------- window-reverse + roll(+3,+3) + residual (exact fp32) ----------------
__global__ void winrev_kernel(const float* __restrict__ y, const float* __restrict__ xT,
                              float* __restrict__ xres) {
    int idx = blockIdx.x * blockDim.x + threadIdx.x;
    if (idx >= TOK * (C_ / 4)) return;
    int t = idx / (C_ / 4);
    int c4 = (idx % (C_ / 4)) * 4;
    int bb = t / (H_ * W_), hw = t % (H_ * W_);
    int h = hw / W_, w = hw % W_;
    int h2 = (h + H_ - 3) % H_;
    int w2 = (w + W_ - 3) % W_;
    int row = (bb * 64 + (h2 / 7) * 8 + (w2 / 7)) * N_ + (h2 % 7) * 7 + (w2 % 7);
    float4 a = *(const float4*)(xT + (size_t)t * C_ + c4);
    float4 yy = *(const float4*)(y + (size_t)row * C_ + c4);
    a.x += yy.x; a.y += yy.y; a.z += yy.z; a.w += yy.w;
    *(float4*)(xres + (size_t)t * C_ + c4) = a;
}

// ---------------- launcher ----------------
extern "C" void kernel_launch(void* const* d_in, const int* in_sizes, int n_in,
                              void* d_out, int out_size) {
    (void)in_sizes; (void)n_in; (void)out_size;
    const float* x      = (const float*)d_in[0];
    const float* qkv_w  = (const float*)d_in[1];
    const float* qkv_b  = (const float*)d_in[2];
    const float* proj_w = (const float*)d_in[3];
    const float* proj_b = (const float*)d_in[4];
    const float* rpb    = (const float*)d_in[5];
    const float* n1w    = (const float*)d_in[6];
    const float* n1b    = (const float*)d_in[7];
    const float* n2w    = (const float*)d_in[8];
    const float* n2b    = (const float*)d_in[9];
    const float* fc1w   = (const float*)d_in[10];
    const float* fc1b   = (const float*)d_in[11];
    const float* fc2w   = (const float*)d_in[12];
    const float* fc2b   = (const float*)d_in[13];
    float* out = (float*)d_out;

    float *xT, *a, *attn, *res, *big;
    __half *h1, *h2, *wT;
    cudaGetSymbolAddress((void**)&xT,   g_xT);
    cudaGetSymbolAddress((void**)&a,    g_a);
    cudaGetSymbolAddress((void**)&attn, g_attn);
    cudaGetSymbolAddress((void**)&res,  g_res);
    cudaGetSymbolAddress((void**)&big,  g_big);
    cudaGetSymbolAddress((void**)&h1,   g_h1);
    cudaGetSymbolAddress((void**)&h2,   g_h2);
    cudaGetSymbolAddress((void**)&wT,   g_wT);

    // 0. weight transposes -> half [N][K]
    wtrans_kernel<<<dim3(36, 12), dim3(32, 8)>>>(qkv_w,  wT + QKVT_OFF, 384, 1152);
    wtrans_kernel<<<dim3(12, 12), dim3(32, 8)>>>(proj_w, wT + PROJT_OFF, 384, 384);
    wtrans_kernel<<<dim3(48, 12), dim3(32, 8)>>>(fc1w,   wT + FC1T_OFF, 384, 1536);
    wtrans_kernel<<<dim3(12, 48), dim3(32, 8)>>>(fc2w,   wT + FC2T_OFF, 1536, 384);

    // 1. (B,C,H,W) -> (B,H,W,C)
    transpose_kernel<<<dim3(98, 12, 32), dim3(32, 8)>>>(x, xT, C_, H_ * W_);
    // 2. shift + window partition + LN1 -> half
    ln_win_kernel<<<TOK, 128>>>(xT, n1w, n1b, h1);
    // 3. QKV GEMM (f32 out)
    gemm_h<<<dim3(TOK / 128, 9), 256>>>(h1, wT + QKVT_OFF, qkv_b, big, nullptr,
                                        TOK, 3 * C_, C_, 0);
    // 4. fused window attention (half out)
    attn_kernel<<<dim3(WINS, NH_), 256>>>(big, rpb, h1);
    // 5. proj GEMM (f32 out)
    gemm_h<<<dim3(TOK / 128, 3), 256>>>(h1, wT + PROJT_OFF, proj_b, a, nullptr,
                                        TOK, C_, C_, 0);
    // 6. window reverse + roll back + residual
    winrev_kernel<<<(TOK * (C_ / 4) + 255) / 256, 256>>>(a, xT, res);
    // 7. LN2 -> half
    ln_plain_kernel<<<TOK, 128>>>(res, n2w, n2b, h1);
    // 8. FC1 GEMM + GELU (half out)
    gemm_h<<<dim3(TOK / 128, 12), 256>>>(h1, wT + FC1T_OFF, fc1b, h2, nullptr,
                                         TOK, HID_, C_, 1);
    // 9. FC2 GEMM + residual (f32 out)
    gemm_h<<<dim3(TOK / 128, 3), 256>>>(h2, wT + FC2T_OFF, fc2b, attn, res,
                                        TOK, C_, HID_, 2);
    // 10. (B,H,W,C) -> (B,C,H,W)
    transpose_kernel<<<dim3(12, 98, 32), dim3(32, 8)>>>(attn, out, H_ * W_, C_);
}

// round 13
// speedup vs baseline: 8.5529x; 1.0559x over previous
#include <cuda_runtime.h>
#include <cuda_fp16.h>
#include <cstdint>

// ---------------- constants ----------------
namespace {
constexpr int B_  = 32;
constexpr int C_  = 384;
constexpr int H_  = 56;
constexpr int W_  = 56;
constexpr int WS_ = 7;
constexpr int NH_ = 12;
constexpr int N_  = 49;
constexpr int TOK = B_ * H_ * W_;    // 100352
constexpr int HID_ = 4 * C_;         // 1536
constexpr int WINS = TOK / N_;       // 2048

// weight-transpose scratch offsets (half elements)
constexpr int QKVT_OFF = 0;
constexpr int PROJT_OFF = 442368;            // 1152*384
constexpr int FC1T_OFF = 589824;             // + 384*384
constexpr int FC2T_OFF = 1179648;            // + 1536*384
}

// ---------------- scratch (device globals; no runtime allocation) ----------------
__device__ float  g_xT[TOK * C_];        // x in (B,H,W,C) layout (shortcut)
__device__ float  g_a[TOK * C_];         // proj out (f32)
__device__ float  g_attn[TOK * C_];      // final pre-transpose (f32)
__device__ float  g_res[TOK * C_];       // residual after attention branch
__device__ float  g_big[TOK * 3 * C_];   // qkv out (f32)
__device__ __half g_h1[TOK * C_];        // half A-operand: ln1 out / attn out / ln2 out
__device__ __half g_h2[TOK * HID_];      // half A-operand: fc1+gelu out
__device__ __half g_wT[1769472];         // all transposed weights (half, [N][K])

#define LDSM4(r0, r1, r2, r3, addr) \
    asm volatile("ldmatrix.sync.aligned.m8n8.x4.shared.b16 {%0,%1,%2,%3}, [%4];" \
                 : "=r"(r0), "=r"(r1), "=r"(r2), "=r"(r3) : "r"(addr))

// ---------------- tiled batch transpose ----------------
__global__ void transpose_kernel(const float* __restrict__ src, float* __restrict__ dst,
                                 int rows, int cols) {
    __shared__ float t[32][33];
    int b = blockIdx.z;
    const float* s = src + (size_t)b * rows * cols;
    float* d = dst + (size_t)b * rows * cols;
    int c0 = blockIdx.x * 32, r0 = blockIdx.y * 32;
    int tx = threadIdx.x, ty = threadIdx.y;
#pragma unroll
    for (int i = 0; i < 32; i += 8)
        t[ty + i][tx] = s[(size_t)(r0 + ty + i) * cols + c0 + tx];
    __syncthreads();
#pragma unroll
    for (int i = 0; i < 32; i += 8)
        d[(size_t)(c0 + ty + i) * rows + r0 + tx] = t[tx][ty + i];
}

// weight transpose + fp16 rounding: src[K][N] f32 -> dst[N][K] half
__global__ void wtrans_kernel(const float* __restrict__ src, __half* __restrict__ dst,
                              int K, int N) {
    __shared__ float t[32][33];
    int n0 = blockIdx.x * 32, k0 = blockIdx.y * 32;
    int tx = threadIdx.x, ty = threadIdx.y;
#pragma unroll
    for (int i = 0; i < 32; i += 8)
        t[ty + i][tx] = src[(size_t)(k0 + ty + i) * N + n0 + tx];
    __syncthreads();
#pragma unroll
    for (int i = 0; i < 32; i += 8)
        dst[(size_t)(n0 + ty + i) * K + k0 + tx] = __float2half_rn(t[tx][ty + i]);
}

// ---------------- LayerNorm ----------------
__device__ __forceinline__ void block_ln_stats_128(float x0, float x1, float x2,
                                                   float& mean, float& rstd) {
    __shared__ float red[8];
    float s = x0 + x1 + x2;
    float s2 = x0 * x0 + x1 * x1 + x2 * x2;
#pragma unroll
    for (int o = 16; o > 0; o >>= 1) {
        s  += __shfl_xor_sync(0xffffffffu, s, o);
        s2 += __shfl_xor_sync(0xffffffffu, s2, o);
    }
    int w = threadIdx.x >> 5;
    if ((threadIdx.x & 31) == 0) { red[w] = s; red[4 + w] = s2; }
    __syncthreads();
    s  = red[0] + red[1] + red[2] + red[3];
    s2 = red[4] + red[5] + red[6] + red[7];
    mean = s * (1.0f / 384.0f);
    float var = s2 * (1.0f / 384.0f) - mean * mean;
    rstd = rsqrtf(var + 1e-5f);
}

// shift + window partition + LN1 -> half (feeds QKV GEMM)
__global__ __launch_bounds__(128) void ln_win_kernel(const float* __restrict__ xT,
                                                     const float* __restrict__ g,
                                                     const float* __restrict__ b,
                                                     __half* __restrict__ out) {
    int r = blockIdx.x;
    int win = r / N_, n = r % N_;
    int bb = win >> 6, wi = win & 63;
    int wh = wi >> 3, ww = wi & 7;
    int i = n / WS_, j = n % WS_;
    int hs = (wh * WS_ + i + 3) % H_;
    int ws = (ww * WS_ + j + 3) % W_;
    const float* src = xT + ((size_t)(bb * H_ + hs) * W_ + ws) * C_;
    int t = threadIdx.x;
    float x0 = src[t], x1 = src[t + 128], x2 = src[t + 256];
    float mean, rstd;
    block_ln_stats_128(x0, x1, x2, mean, rstd);
    __half* o = out + (size_t)r * C_;
    o[t]       = __float2half_rn((x0 - mean) * rstd * g[t]       + b[t]);
    o[t + 128] = __float2half_rn((x1 - mean) * rstd * g[t + 128] + b[t + 128]);
    o[t + 256] = __float2half_rn((x2 - mean) * rstd * g[t + 256] + b[t + 256]);
}

// fused: window-reverse + roll(+3,+3) + residual -> res (f32), then LN2 -> half
__global__ __launch_bounds__(128) void ln_winrev_kernel(const float* __restrict__ y,
                                                        const float* __restrict__ xT,
                                                        const float* __restrict__ g,
                                                        const float* __restrict__ b,
                                                        float* __restrict__ res,
                                                        __half* __restrict__ out) {
    int tk = blockIdx.x;
    int bb = tk / (H_ * W_), hw = tk % (H_ * W_);
    int h = hw / W_, w = hw % W_;
    int h2 = (h + H_ - 3) % H_;
    int w2 = (w + W_ - 3) % W_;
    int row = (bb * 64 + (h2 / 7) * 8 + (w2 / 7)) * N_ + (h2 % 7) * 7 + (w2 % 7);
    const float* yr = y + (size_t)row * C_;
    const float* xr = xT + (size_t)tk * C_;
    int t = threadIdx.x;
    float x0 = xr[t]       + yr[t];
    float x1 = xr[t + 128] + yr[t + 128];
    float x2 = xr[t + 256] + yr[t + 256];
    float* rr = res + (size_t)tk * C_;
    rr[t] = x0; rr[t + 128] = x1; rr[t + 256] = x2;
    float mean, rstd;
    block_ln_stats_128(x0, x1, x2, mean, rstd);
    __half* o = out + (size_t)tk * C_;
    o[t]       = __float2half_rn((x0 - mean) * rstd * g[t]       + b[t]);
    o[t + 128] = __float2half_rn((x1 - mean) * rstd * g[t + 128] + b[t + 128]);
    o[t + 256] = __float2half_rn((x2 - mean) * rstd * g[t + 256] + b[t + 256]);
}

// ---------------- FP16 tensor-core GEMM (mma.sync.m16n8k16 + ldmatrix) ----------------
// C[M,Nn] = A[M,K] @ Bt[Nn,K]^T + bias
// epi: 0 = bias -> f32 out; 1 = bias + exact GELU -> half out; 2 = bias + resid -> f32 out
// M%128==0, Nn%128==0, K%32==0. A, Bt are half.
// Block tile 128x128x32, 256 threads = 8 warps (4 m x 2 n), warp tile 32x64.
__global__ __launch_bounds__(256) void gemm_h(const __half* __restrict__ A,
                                              const __half* __restrict__ Bt,
                                              const float* __restrict__ bias,
                                              void* __restrict__ Cm,
                                              const float* __restrict__ resid,
                                              int M, int Nn, int K, int epi) {
    // [row][k] layout, row stride 40 halves (80B): LDSM phases cover banks 0..31 exactly
    __shared__ __align__(16) __half As[2][128][40];
    __shared__ __align__(16) __half Bs[2][128][40];

    int tid  = threadIdx.x;
    int lane = tid & 31, warp = tid >> 5;
    int wm = (warp & 3) * 32;
    int wn = (warp >> 2) * 64;
    int m0 = blockIdx.x * 128, n0 = blockIdx.y * 128;

    int lr = tid >> 1;           // 0..127 tile row
    int lc = (tid & 1) * 16;     // 0 or 16 (half index within 32-wide k tile)
    const __half* gA = A  + (size_t)(m0 + lr) * K + lc;
    const __half* gB = Bt + (size_t)(n0 + lr) * K + lc;

    // ldmatrix per-lane smem byte offsets
    uint32_t asBase = (uint32_t)__cvta_generic_to_shared(&As[0][0][0]);
    uint32_t bsBase = (uint32_t)__cvta_generic_to_shared(&Bs[0][0][0]);
    int lane15 = lane & 15, lanehi = lane >> 4;
    uint32_t aoff[2], boff[4];
#pragma unroll
    for (int i = 0; i < 2; i++)
        aoff[i] = (uint32_t)(((wm + 16 * i + lane15) * 40 + 8 * lanehi) * 2);
#pragma unroll
    for (int j2 = 0; j2 < 4; j2++)
        boff[j2] = (uint32_t)(((wn + 16 * j2 + lane15) * 40 + 8 * lanehi) * 2);

    float c[2][8][4];
#pragma unroll
    for (int i = 0; i < 2; i++)
#pragma unroll
        for (int j = 0; j < 8; j++)
#pragma unroll
            for (int q = 0; q < 4; q++) c[i][j][q] = 0.0f;

    const int nIter = K >> 5;
    uint4 pa0, pa1, pb0, pb1;

    // prologue: tile 0 -> buf 0
    pa0 = *(const uint4*)(gA);
    pa1 = *(const uint4*)(gA + 8);
    pb0 = *(const uint4*)(gB);
    pb1 = *(const uint4*)(gB + 8);
    *(uint4*)&As[0][lr][lc]     = pa0;
    *(uint4*)&As[0][lr][lc + 8] = pa1;
    *(uint4*)&Bs[0][lr][lc]     = pb0;
    *(uint4*)&Bs[0][lr][lc + 8] = pb1;
    __syncthreads();

    for (int it = 0; it < nIter; ++it) {
        int buf = it & 1;
        bool more = (it + 1) < nIter;
        if (more) {
            const __half* ga = gA + (size_t)(it + 1) * 32;
            const __half* gb = gB + (size_t)(it + 1) * 32;
            pa0 = *(const uint4*)(ga);
            pa1 = *(const uint4*)(ga + 8);
            pb0 = *(const uint4*)(gb);
            pb1 = *(const uint4*)(gb + 8);
        }
        uint32_t aB = asBase + (uint32_t)buf * 10240u;
        uint32_t bB = bsBase + (uint32_t)buf * 10240u;
#pragma unroll
        for (int ks2 = 0; ks2 < 64; ks2 += 32) {   // ks in bytes: 0, 32 (= k 0, 16)
            uint32_t af[2][4];
#pragma unroll
            for (int i = 0; i < 2; i++)
                LDSM4(af[i][0], af[i][1], af[i][2], af[i][3], aB + aoff[i] + ks2);
            uint32_t bf[8][2];
#pragma unroll
            for (int j2 = 0; j2 < 4; j2++)
                LDSM4(bf[2 * j2][0], bf[2 * j2 + 1][0], bf[2 * j2][1], bf[2 * j2 + 1][1],
                      bB + boff[j2] + ks2);
#pragma unroll
            for (int i = 0; i < 2; i++)
#pragma unroll
                for (int j = 0; j < 8; j++)
                    asm volatile(
                        "mma.sync.aligned.m16n8k16.row.col.f32.f16.f16.f32 "
                        "{%0,%1,%2,%3}, {%4,%5,%6,%7}, {%8,%9}, {%0,%1,%2,%3};"
                        : "+f"(c[i][j][0]), "+f"(c[i][j][1]),
                          "+f"(c[i][j][2]), "+f"(c[i][j][3])
                        : "r"(af[i][0]), "r"(af[i][1]), "r"(af[i][2]), "r"(af[i][3]),
                          "r"(bf[j][0]), "r"(bf[j][1]));
        }
        if (more) {
            int nb = buf ^ 1;
            __syncthreads();
            *(uint4*)&As[nb][lr][lc]     = pa0;
            *(uint4*)&As[nb][lr][lc + 8] = pa1;
            *(uint4*)&Bs[nb][lr][lc]     = pb0;
            *(uint4*)&Bs[nb][lr][lc + 8] = pb1;
            __syncthreads();
        }
    }

    // epilogue
    int g = lane >> 2, t = lane & 3;
    float* Cf = (float*)Cm;
    __half* Ch = (__half*)Cm;
#pragma unroll
    for (int i = 0; i < 2; i++) {
        int rA = m0 + wm + 16 * i + g;
#pragma unroll
        for (int j = 0; j < 8; j++) {
            int col = n0 + wn + 8 * j + 2 * t;
            float b0 = bias[col], b1 = bias[col + 1];
            float v0 = c[i][j][0] + b0;
            float v1 = c[i][j][1] + b1;
            float v2 = c[i][j][2] + b0;
            float v3 = c[i][j][3] + b1;
            if (epi == 1) {
                v0 = 0.5f * v0 * (1.0f + erff(v0 * 0.70710678118654752f));
                v1 = 0.5f * v1 * (1.0f + erff(v1 * 0.70710678118654752f));
                v2 = 0.5f * v2 * (1.0f + erff(v2 * 0.70710678118654752f));
                v3 = 0.5f * v3 * (1.0f + erff(v3 * 0.70710678118654752f));
                *(__half2*)(Ch + (size_t)rA * Nn + col) =
                    __floats2half2_rn(v0, v1);
                *(__half2*)(Ch + (size_t)(rA + 8) * Nn + col) =
                    __floats2half2_rn(v2, v3);
            } else {
                if (epi == 2) {
                    float2 r0 = *(const float2*)(resid + (size_t)rA * Nn + col);
                    float2 r1 = *(const float2*)(resid + (size_t)(rA + 8) * Nn + col);
                    v0 += r0.x; v1 += r0.y; v2 += r1.x; v3 += r1.y;
                }
                *(float2*)(Cf + (size_t)rA * Nn + col)       = make_float2(v0, v1);
                *(float2*)(Cf + (size_t)(rA + 8) * Nn + col) = make_float2(v2, v3);
            }
        }
    }
}

// ---------------- fused window attention (fp32 math; half output for proj GEMM) ------
__global__ __launch_bounds__(256) void attn_kernel(const float* __restrict__ qkv,
                                                   const float* __restrict__ rpb,
                                                   __half* __restrict__ outp) {
    int win = blockIdx.x;
    int head = blockIdx.y;
    __shared__ float q[49][33], k[49][33], v[49][33];
    __shared__ float S[49][50];
    int tid = threadIdx.x;
    const float* base = qkv + (size_t)win * N_ * (3 * C_) + head * 32;
    for (int idx = tid; idx < 49 * 32; idx += 256) {
        int n = idx >> 5, d = idx & 31;
        const float* row = base + (size_t)n * (3 * C_);
        q[n][d] = row[d] * 0.17677669529663689f;
        k[n][d] = row[C_ + d];
        v[n][d] = row[2 * C_ + d];
    }
    __syncthreads();

    int wi = win & 63;
    int wh = wi >> 3, ww = wi & 7;
    for (int p = tid; p < 49 * 49; p += 256) {
        int n = p / 49, m = p % 49;
        float s = 0.0f;
#pragma unroll
        for (int d = 0; d < 32; d++) s += q[n][d] * k[m][d];
        int i1 = n / 7, j1 = n % 7, i2 = m / 7, j2 = m % 7;
        int ridx = (i1 - i2 + 6) * 13 + (j1 - j2 + 6);
        s += rpb[ridx * NH_ + head];
        int h1 = wh * 7 + i1, w1 = ww * 7 + j1;
        int h2 = wh * 7 + i2, w2 = ww * 7 + j2;
        int r1 = (h1 < 49 ? 0 : (h1 < 53 ? 1 : 2)) * 3 + (w1 < 49 ? 0 : (w1 < 53 ? 1 : 2));
        int r2 = (h2 < 49 ? 0 : (h2 < 53 ? 1 : 2)) * 3 + (w2 < 49 ? 0 : (w2 < 53 ? 1 : 2));
        if (r1 != r2) s -= 100.0f;
        S[n][m] = s;
    }
    __syncthreads();

    if (tid < 49) {
        float mx = -1e30f;
#pragma unroll 7
        for (int m = 0; m < 49; m++) mx = fmaxf(mx, S[tid][m]);
        float sum = 0.0f;
#pragma unroll 7
        for (int m = 0; m < 49; m++) {
            float e = __expf(S[tid][m] - mx);
            S[tid][m] = e;
            sum += e;
        }
        float inv = 1.0f / sum;
#pragma unroll 7
        for (int m = 0; m < 49; m++) S[tid][m] *= inv;
    }
    __syncthreads();

    for (int p = tid; p < 49 * 32; p += 256) {
        int n = p >> 5, d = p & 31;
        float o = 0.0f;
#pragma unroll 7
        for (int m = 0; m < 49; m++) o += S[n][m] * v[m][d];
        outp[((size_t)win * N_ + n) * C_ + head * 32 + d] = __float2half_rn(o);
    }
}

// ---------------- launcher ----------------
extern "C" void kernel_launch(void* const* d_in, const int* in_sizes, int n_in,
                              void* d_out, int out_size) {
    (void)in_sizes; (void)n_in; (void)out_size;
    const float* x      = (const float*)d_in[0];
    const float* qkv_w  = (const float*)d_in[1];
    const float* qkv_b  = (const float*)d_in[2];
    const float* proj_w = (const float*)d_in[3];
    const float* proj_b = (const float*)d_in[4];
    const float* rpb    = (const float*)d_in[5];
    const float* n1w    = (const float*)d_in[6];
    const float* n1b    = (const float*)d_in[7];
    const float* n2w    = (const float*)d_in[8];
    const float* n2b    = (const float*)d_in[9];
    const float* fc1w   = (const float*)d_in[10];
    const float* fc1b   = (const float*)d_in[11];
    const float* fc2w   = (const float*)d_in[12];
    const float* fc2b   = (const float*)d_in[13];
    float* out = (float*)d_out;

    float *xT, *a, *attn, *res, *big;
    __half *h1, *h2, *wT;
    cudaGetSymbolAddress((void**)&xT,   g_xT);
    cudaGetSymbolAddress((void**)&a,    g_a);
    cudaGetSymbolAddress((void**)&attn, g_attn);
    cudaGetSymbolAddress((void**)&res,  g_res);
    cudaGetSymbolAddress((void**)&big,  g_big);
    cudaGetSymbolAddress((void**)&h1,   g_h1);
    cudaGetSymbolAddress((void**)&h2,   g_h2);
    cudaGetSymbolAddress((void**)&wT,   g_wT);

    // 0. weight transposes -> half [N][K]
    wtrans_kernel<<<dim3(36, 12), dim3(32, 8)>>>(qkv_w,  wT + QKVT_OFF, 384, 1152);
    wtrans_kernel<<<dim3(12, 12), dim3(32, 8)>>>(proj_w, wT + PROJT_OFF, 384, 384);
    wtrans_kernel<<<dim3(48, 12), dim3(32, 8)>>>(fc1w,   wT + FC1T_OFF, 384, 1536);
    wtrans_kernel<<<dim3(12, 48), dim3(32, 8)>>>(fc2w,   wT + FC2T_OFF, 1536, 384);

    // 1. (B,C,H,W) -> (B,H,W,C)
    transpose_kernel<<<dim3(98, 12, 32), dim3(32, 8)>>>(x, xT, C_, H_ * W_);
    // 2. shift + window partition + LN1 -> half
    ln_win_kernel<<<TOK, 128>>>(xT, n1w, n1b, h1);
    // 3. QKV GEMM (f32 out)
    gemm_h<<<dim3(TOK / 128, 9), 256>>>(h1, wT + QKVT_OFF, qkv_b, big, nullptr,
                                        TOK, 3 * C_, C_, 0);
    // 4. fused window attention (half out)
    attn_kernel<<<dim3(WINS, NH_), 256>>>(big, rpb, h1);
    // 5. proj GEMM (f32 out)
    gemm_h<<<dim3(TOK / 128, 3), 256>>>(h1, wT + PROJT_OFF, proj_b, a, nullptr,
                                        TOK, C_, C_, 0);
    // 6+7. window reverse + roll + residual + LN2 (fused; res f32, ln half)
    ln_winrev_kernel<<<TOK, 128>>>(a, xT, n2w, n2b, res, h1);
    // 8. FC1 GEMM + GELU (half out)
    gemm_h<<<dim3(TOK / 128, 12), 256>>>(h1, wT + FC1T_OFF, fc1b, h2, nullptr,
                                         TOK, HID_, C_, 1);
    // 9. FC2 GEMM + residual (f32 out)
    gemm_h<<<dim3(TOK / 128, 3), 256>>>(h2, wT + FC2T_OFF, fc2b, attn, res,
                                        TOK, C_, HID_, 2);
    // 10. (B,H,W,C) -> (B,C,H,W)
    transpose_kernel<<<dim3(12, 98, 32), dim3(32, 8)>>>(attn, out, H_ * W_, C_);
}

// round 14
// speedup vs baseline: 9.3189x; 1.0896x over previous
#include <cuda_runtime.h>
#include <cuda_fp16.h>
#include <cstdint>

// ---------------- constants ----------------
namespace {
constexpr int B_  = 32;
constexpr int C_  = 384;
constexpr int H_  = 56;
constexpr int W_  = 56;
constexpr int WS_ = 7;
constexpr int NH_ = 12;
constexpr int N_  = 49;
constexpr int TOK = B_ * H_ * W_;    // 100352
constexpr int HID_ = 4 * C_;         // 1536
constexpr int WINS = TOK / N_;       // 2048
constexpr int NS = 3;                // cp.async pipeline stages

// weight-transpose scratch offsets (half elements)
constexpr int QKVT_OFF = 0;
constexpr int PROJT_OFF = 442368;            // 1152*384
constexpr int FC1T_OFF = 589824;             // + 384*384
constexpr int FC2T_OFF = 1179648;            // + 1536*384
}

// ---------------- scratch (device globals; no runtime allocation) ----------------
__device__ float  g_xT[TOK * C_];        // x in (B,H,W,C) layout (shortcut)
__device__ float  g_a[TOK * C_];         // proj out (f32)
__device__ float  g_attn[TOK * C_];      // final pre-transpose (f32)
__device__ float  g_res[TOK * C_];       // residual after attention branch
__device__ __half g_h1[TOK * C_];        // half: ln1 out / attn out / ln2 out
__device__ __half g_h2[TOK * HID_];      // half: qkv out (w=1152), later fc1+gelu out (w=1536)
__device__ __half g_wT[1769472];         // all transposed weights (half, [N][K])

#define LDSM4(r0, r1, r2, r3, addr) \
    asm volatile("ldmatrix.sync.aligned.m8n8.x4.shared.b16 {%0,%1,%2,%3}, [%4];" \
                 : "=r"(r0), "=r"(r1), "=r"(r2), "=r"(r3) : "r"(addr))

__device__ __forceinline__ void cp16(uint32_t saddr, const void* gaddr) {
    asm volatile("cp.async.cg.shared.global [%0], [%1], 16;" :: "r"(saddr), "l"(gaddr));
}

// ---------------- tiled batch transpose ----------------
__global__ void transpose_kernel(const float* __restrict__ src, float* __restrict__ dst,
                                 int rows, int cols) {
    __shared__ float t[32][33];
    int b = blockIdx.z;
    const float* s = src + (size_t)b * rows * cols;
    float* d = dst + (size_t)b * rows * cols;
    int c0 = blockIdx.x * 32, r0 = blockIdx.y * 32;
    int tx = threadIdx.x, ty = threadIdx.y;
#pragma unroll
    for (int i = 0; i < 32; i += 8)
        t[ty + i][tx] = s[(size_t)(r0 + ty + i) * cols + c0 + tx];
    __syncthreads();
#pragma unroll
    for (int i = 0; i < 32; i += 8)
        d[(size_t)(c0 + ty + i) * rows + r0 + tx] = t[tx][ty + i];
}

// weight transpose + fp16 rounding: src[K][N] f32 -> dst[N][K] half
__global__ void wtrans_kernel(const float* __restrict__ src, __half* __restrict__ dst,
                              int K, int N) {
    __shared__ float t[32][33];
    int n0 = blockIdx.x * 32, k0 = blockIdx.y * 32;
    int tx = threadIdx.x, ty = threadIdx.y;
#pragma unroll
    for (int i = 0; i < 32; i += 8)
        t[ty + i][tx] = src[(size_t)(k0 + ty + i) * N + n0 + tx];
    __syncthreads();
#pragma unroll
    for (int i = 0; i < 32; i += 8)
        dst[(size_t)(n0 + ty + i) * K + k0 + tx] = __float2half_rn(t[tx][ty + i]);
}

// ---------------- LayerNorm ----------------
__device__ __forceinline__ void block_ln_stats_128(float x0, float x1, float x2,
                                                   float& mean, float& rstd) {
    __shared__ float red[8];
    float s = x0 + x1 + x2;
    float s2 = x0 * x0 + x1 * x1 + x2 * x2;
#pragma unroll
    for (int o = 16; o > 0; o >>= 1) {
        s  += __shfl_xor_sync(0xffffffffu, s, o);
        s2 += __shfl_xor_sync(0xffffffffu, s2, o);
    }
    int w = threadIdx.x >> 5;
    if ((threadIdx.x & 31) == 0) { red[w] = s; red[4 + w] = s2; }
    __syncthreads();
    s  = red[0] + red[1] + red[2] + red[3];
    s2 = red[4] + red[5] + red[6] + red[7];
    mean = s * (1.0f / 384.0f);
    float var = s2 * (1.0f / 384.0f) - mean * mean;
    rstd = rsqrtf(var + 1e-5f);
}

// shift + window partition + LN1 -> half (feeds QKV GEMM)
__global__ __launch_bounds__(128) void ln_win_kernel(const float* __restrict__ xT,
                                                     const float* __restrict__ g,
                                                     const float* __restrict__ b,
                                                     __half* __restrict__ out) {
    int r = blockIdx.x;
    int win = r / N_, n = r % N_;
    int bb = win >> 6, wi = win & 63;
    int wh = wi >> 3, ww = wi & 7;
    int i = n / WS_, j = n % WS_;
    int hs = (wh * WS_ + i + 3) % H_;
    int ws = (ww * WS_ + j + 3) % W_;
    const float* src = xT + ((size_t)(bb * H_ + hs) * W_ + ws) * C_;
    int t = threadIdx.x;
    float x0 = src[t], x1 = src[t + 128], x2 = src[t + 256];
    float mean, rstd;
    block_ln_stats_128(x0, x1, x2, mean, rstd);
    __half* o = out + (size_t)r * C_;
    o[t]       = __float2half_rn((x0 - mean) * rstd * g[t]       + b[t]);
    o[t + 128] = __float2half_rn((x1 - mean) * rstd * g[t + 128] + b[t + 128]);
    o[t + 256] = __float2half_rn((x2 - mean) * rstd * g[t + 256] + b[t + 256]);
}

// fused: window-reverse + roll(+3,+3) + residual -> res (f32), then LN2 -> half
__global__ __launch_bounds__(128) void ln_winrev_kernel(const float* __restrict__ y,
                                                        const float* __restrict__ xT,
                                                        const float* __restrict__ g,
                                                        const float* __restrict__ b,
                                                        float* __restrict__ res,
                                                        __half* __restrict__ out) {
    int tk = blockIdx.x;
    int bb = tk / (H_ * W_), hw = tk % (H_ * W_);
    int h = hw / W_, w = hw % W_;
    int h2 = (h + H_ - 3) % H_;
    int w2 = (w + W_ - 3) % W_;
    int row = (bb * 64 + (h2 / 7) * 8 + (w2 / 7)) * N_ + (h2 % 7) * 7 + (w2 % 7);
    const float* yr = y + (size_t)row * C_;
    const float* xr = xT + (size_t)tk * C_;
    int t = threadIdx.x;
    float x0 = xr[t]       + yr[t];
    float x1 = xr[t + 128] + yr[t + 128];
    float x2 = xr[t + 256] + yr[t + 256];
    float* rr = res + (size_t)tk * C_;
    rr[t] = x0; rr[t + 128] = x1; rr[t + 256] = x2;
    float mean, rstd;
    block_ln_stats_128(x0, x1, x2, mean, rstd);
    __half* o = out + (size_t)tk * C_;
    o[t]       = __float2half_rn((x0 - mean) * rstd * g[t]       + b[t]);
    o[t + 128] = __float2half_rn((x1 - mean) * rstd * g[t + 128] + b[t + 128]);
    o[t + 256] = __float2half_rn((x2 - mean) * rstd * g[t + 256] + b[t + 256]);
}

// ---------------- FP16 tensor-core GEMM (mma.sync.m16n8k16 + ldmatrix + cp.async) ----
// C[M,Nn] = A[M,K] @ Bt[Nn,K]^T + bias
// epi: 0 = bias -> f32; 1 = bias + exact GELU -> half; 2 = bias + resid -> f32;
//      3 = bias -> half
// M%128==0, Nn%128==0, K%32==0. A, Bt are half.
// Block tile 128x128x32, 256 threads = 8 warps (4 m x 2 n), warp tile 32x64.
// 3-stage cp.async pipeline, one __syncthreads per K-iteration.
__global__ __launch_bounds__(256) void gemm_h(const __half* __restrict__ A,
                                              const __half* __restrict__ Bt,
                                              const float* __restrict__ bias,
                                              void* __restrict__ Cm,
                                              const float* __restrict__ resid,
                                              int M, int Nn, int K, int epi) {
    // [row][k] layout, row stride 40 halves (80B): LDSM phases cover banks 0..31 exactly
    __shared__ __align__(16) __half As[NS][128][40];
    __shared__ __align__(16) __half Bs[NS][128][40];

    int tid  = threadIdx.x;
    int lane = tid & 31, warp = tid >> 5;
    int wm = (warp & 3) * 32;
    int wn = (warp >> 2) * 64;
    int m0 = blockIdx.x * 128, n0 = blockIdx.y * 128;

    int lr = tid >> 1;           // 0..127 tile row
    int lc = (tid & 1) * 16;     // 0 or 16 (half index within 32-wide k tile)
    const __half* gA = A  + (size_t)(m0 + lr) * K + lc;
    const __half* gB = Bt + (size_t)(n0 + lr) * K + lc;

    uint32_t asBase = (uint32_t)__cvta_generic_to_shared(&As[0][0][0]);
    uint32_t bsBase = (uint32_t)__cvta_generic_to_shared(&Bs[0][0][0]);
    uint32_t stoff = (uint32_t)(lr * 80 + lc * 2);   // byte offset of this thread's chunk

    // ldmatrix per-lane smem byte offsets
    int lane15 = lane & 15, lanehi = lane >> 4;
    uint32_t aoff[2], boff[4];
#pragma unroll
    for (int i = 0; i < 2; i++)
        aoff[i] = (uint32_t)(((wm + 16 * i + lane15) * 40 + 8 * lanehi) * 2);
#pragma unroll
    for (int j2 = 0; j2 < 4; j2++)
        boff[j2] = (uint32_t)(((wn + 16 * j2 + lane15) * 40 + 8 * lanehi) * 2);

    float c[2][8][4];
#pragma unroll
    for (int i = 0; i < 2; i++)
#pragma unroll
        for (int j = 0; j < 8; j++)
#pragma unroll
            for (int q = 0; q < 4; q++) c[i][j][q] = 0.0f;

    const int nIter = K >> 5;

    // always commits (possibly-empty group) so wait_group<NS-2> semantics hold at tail
    auto load_stage = [&](int s) {
        if (s < nIter) {
            uint32_t sa = asBase + (uint32_t)(s % NS) * 10240u + stoff;
            uint32_t sb = bsBase + (uint32_t)(s % NS) * 10240u + stoff;
            const __half* ga = gA + (size_t)s * 32;
            const __half* gb = gB + (size_t)s * 32;
            cp16(sa, ga);
            cp16(sa + 16u, ga + 8);
            cp16(sb, gb);
            cp16(sb + 16u, gb + 8);
        }
        asm volatile("cp.async.commit_group;" ::: "memory");
    };

#pragma unroll
    for (int s = 0; s < NS - 1; s++) load_stage(s);

    for (int it = 0; it < nIter; ++it) {
        asm volatile("cp.async.wait_group %0;" :: "n"(NS - 2) : "memory");
        __syncthreads();
        load_stage(it + NS - 1);

        uint32_t aB = asBase + (uint32_t)(it % NS) * 10240u;
        uint32_t bB = bsBase + (uint32_t)(it % NS) * 10240u;
#pragma unroll
        for (int ks2 = 0; ks2 < 64; ks2 += 32) {   // bytes: 0, 32 (= k 0, 16)
            uint32_t af[2][4];
#pragma unroll
            for (int i = 0; i < 2; i++)
                LDSM4(af[i][0], af[i][1], af[i][2], af[i][3], aB + aoff[i] + ks2);
            uint32_t bf[8][2];
#pragma unroll
            for (int j2 = 0; j2 < 4; j2++)
                LDSM4(bf[2 * j2][0], bf[2 * j2 + 1][0], bf[2 * j2][1], bf[2 * j2 + 1][1],
                      bB + boff[j2] + ks2);
#pragma unroll
            for (int i = 0; i < 2; i++)
#pragma unroll
                for (int j = 0; j < 8; j++)
                    asm volatile(
                        "mma.sync.aligned.m16n8k16.row.col.f32.f16.f16.f32 "
                        "{%0,%1,%2,%3}, {%4,%5,%6,%7}, {%8,%9}, {%0,%1,%2,%3};"
                        : "+f"(c[i][j][0]), "+f"(c[i][j][1]),
                          "+f"(c[i][j][2]), "+f"(c[i][j][3])
                        : "r"(af[i][0]), "r"(af[i][1]), "r"(af[i][2]), "r"(af[i][3]),
                          "r"(bf[j][0]), "r"(bf[j][1]));
        }
    }

    // epilogue
    int g = lane >> 2, t = lane & 3;
    float* Cf = (float*)Cm;
    __half* Ch = (__half*)Cm;
#pragma unroll
    for (int i = 0; i < 2; i++) {
        int rA = m0 + wm + 16 * i + g;
#pragma unroll
        for (int j = 0; j < 8; j++) {
            int col = n0 + wn + 8 * j + 2 * t;
            float b0 = bias[col], b1 = bias[col + 1];
            float v0 = c[i][j][0] + b0;
            float v1 = c[i][j][1] + b1;
            float v2 = c[i][j][2] + b0;
            float v3 = c[i][j][3] + b1;
            if (epi == 1) {
                v0 = 0.5f * v0 * (1.0f + erff(v0 * 0.70710678118654752f));
                v1 = 0.5f * v1 * (1.0f + erff(v1 * 0.70710678118654752f));
                v2 = 0.5f * v2 * (1.0f + erff(v2 * 0.70710678118654752f));
                v3 = 0.5f * v3 * (1.0f + erff(v3 * 0.70710678118654752f));
            }
            if (epi == 1 || epi == 3) {
                *(__half2*)(Ch + (size_t)rA * Nn + col) =
                    __floats2half2_rn(v0, v1);
                *(__half2*)(Ch + (size_t)(rA + 8) * Nn + col) =
                    __floats2half2_rn(v2, v3);
            } else {
                if (epi == 2) {
                    float2 r0 = *(const float2*)(resid + (size_t)rA * Nn + col);
                    float2 r1 = *(const float2*)(resid + (size_t)(rA + 8) * Nn + col);
                    v0 += r0.x; v1 += r0.y; v2 += r1.x; v3 += r1.y;
                }
                *(float2*)(Cf + (size_t)rA * Nn + col)       = make_float2(v0, v1);
                *(float2*)(Cf + (size_t)(rA + 8) * Nn + col) = make_float2(v2, v3);
            }
        }
    }
}

// ---------------- fused window attention (half in, fp32 math, half out) ----------------
__global__ __launch_bounds__(256) void attn_kernel(const __half* __restrict__ qkv,
                                                   const float* __restrict__ rpb,
                                                   __half* __restrict__ outp) {
    int win = blockIdx.x;
    int head = blockIdx.y;
    __shared__ float q[49][33], k[49][33], v[49][33];
    __shared__ float S[49][50];
    int tid = threadIdx.x;
    const __half* base = qkv + (size_t)win * N_ * (3 * C_) + head * 32;
    for (int idx = tid; idx < 49 * 32; idx += 256) {
        int n = idx >> 5, d = idx & 31;
        const __half* row = base + (size_t)n * (3 * C_);
        q[n][d] = __half2float(row[d]) * 0.17677669529663689f;
        k[n][d] = __half2float(row[C_ + d]);
        v[n][d] = __half2float(row[2 * C_ + d]);
    }
    __syncthreads();

    int wi = win & 63;
    int wh = wi >> 3, ww = wi & 7;
    for (int p = tid; p < 49 * 49; p += 256) {
        int n = p / 49, m = p % 49;
        float s = 0.0f;
#pragma unroll
        for (int d = 0; d < 32; d++) s += q[n][d] * k[m][d];
        int i1 = n / 7, j1 = n % 7, i2 = m / 7, j2 = m % 7;
        int ridx = (i1 - i2 + 6) * 13 + (j1 - j2 + 6);
        s += rpb[ridx * NH_ + head];
        int h1 = wh * 7 + i1, w1 = ww * 7 + j1;
        int h2 = wh * 7 + i2, w2 = ww * 7 + j2;
        int r1 = (h1 < 49 ? 0 : (h1 < 53 ? 1 : 2)) * 3 + (w1 < 49 ? 0 : (w1 < 53 ? 1 : 2));
        int r2 = (h2 < 49 ? 0 : (h2 < 53 ? 1 : 2)) * 3 + (w2 < 49 ? 0 : (w2 < 53 ? 1 : 2));
        if (r1 != r2) s -= 100.0f;
        S[n][m] = s;
    }
    __syncthreads();

    if (tid < 49) {
        float mx = -1e30f;
#pragma unroll 7
        for (int m = 0; m < 49; m++) mx = fmaxf(mx, S[tid][m]);
        float sum = 0.0f;
#pragma unroll 7
        for (int m = 0; m < 49; m++) {
            float e = __expf(S[tid][m] - mx);
            S[tid][m] = e;
            sum += e;
        }
        float inv = 1.0f / sum;
#pragma unroll 7
        for (int m = 0; m < 49; m++) S[tid][m] *= inv;
    }
    __syncthreads();

    for (int p = tid; p < 49 * 32; p += 256) {
        int n = p >> 5, d = p & 31;
        float o = 0.0f;
#pragma unroll 7
        for (int m = 0; m < 49; m++) o += S[n][m] * v[m][d];
        outp[((size_t)win * N_ + n) * C_ + head * 32 + d] = __float2half_rn(o);
    }
}

// ---------------- launcher ----------------
extern "C" void kernel_launch(void* const* d_in, const int* in_sizes, int n_in,
                              void* d_out, int out_size) {
    (void)in_sizes; (void)n_in; (void)out_size;
    const float* x      = (const float*)d_in[0];
    const float* qkv_w  = (const float*)d_in[1];
    const float* qkv_b  = (const float*)d_in[2];
    const float* proj_w = (const float*)d_in[3];
    const float* proj_b = (const float*)d_in[4];
    const float* rpb    = (const float*)d_in[5];
    const float* n1w    = (const float*)d_in[6];
    const float* n1b    = (const float*)d_in[7];
    const float* n2w    = (const float*)d_in[8];
    const float* n2b    = (const float*)d_in[9];
    const float* fc1w   = (const float*)d_in[10];
    const float* fc1b   = (const float*)d_in[11];
    const float* fc2w   = (const float*)d_in[12];
    const float* fc2b   = (const float*)d_in[13];
    float* out = (float*)d_out;

    float *xT, *a, *attn, *res;
    __half *h1, *h2, *wT;
    cudaGetSymbolAddress((void**)&xT,   g_xT);
    cudaGetSymbolAddress((void**)&a,    g_a);
    cudaGetSymbolAddress((void**)&attn, g_attn);
    cudaGetSymbolAddress((void**)&res,  g_res);
    cudaGetSymbolAddress((void**)&h1,   g_h1);
    cudaGetSymbolAddress((void**)&h2,   g_h2);
    cudaGetSymbolAddress((void**)&wT,   g_wT);

    // 0. weight transposes -> half [N][K]
    wtrans_kernel<<<dim3(36, 12), dim3(32, 8)>>>(qkv_w,  wT + QKVT_OFF, 384, 1152);
    wtrans_kernel<<<dim3(12, 12), dim3(32, 8)>>>(proj_w, wT + PROJT_OFF, 384, 384);
    wtrans_kernel<<<dim3(48, 12), dim3(32, 8)>>>(fc1w,   wT + FC1T_OFF, 384, 1536);
    wtrans_kernel<<<dim3(12, 48), dim3(32, 8)>>>(fc2w,   wT + FC2T_OFF, 1536, 384);

    // 1. (B,C,H,W) -> (B,H,W,C)
    transpose_kernel<<<dim3(98, 12, 32), dim3(32, 8)>>>(x, xT, C_, H_ * W_);
    // 2. shift + window partition + LN1 -> half
    ln_win_kernel<<<TOK, 128>>>(xT, n1w, n1b, h1);
    // 3. QKV GEMM (half out -> h2, width 1152)
    gemm_h<<<dim3(TOK / 128, 9), 256>>>(h1, wT + QKVT_OFF, qkv_b, h2, nullptr,
                                        TOK, 3 * C_, C_, 3);
    // 4. fused window attention (half in/out)
    attn_kernel<<<dim3(WINS, NH_), 256>>>(h2, rpb, h1);
    // 5. proj GEMM (f32 out)
    gemm_h<<<dim3(TOK / 128, 3), 256>>>(h1, wT + PROJT_OFF, proj_b, a, nullptr,
                                        TOK, C_, C_, 0);
    // 6+7. window reverse + roll + residual + LN2 (fused; res f32, ln half)
    ln_winrev_kernel<<<TOK, 128>>>(a, xT, n2w, n2b, res, h1);
    // 8. FC1 GEMM + GELU (half out)
    gemm_h<<<dim3(TOK / 128, 12), 256>>>(h1, wT + FC1T_OFF, fc1b, h2, nullptr,
                                         TOK, HID_, C_, 1);
    // 9. FC2 GEMM + residual (f32 out)
    gemm_h<<<dim3(TOK / 128, 3), 256>>>(h2, wT + FC2T_OFF, fc2b, attn, res,
                                        TOK, C_, HID_, 2);
    // 10. (B,H,W,C) -> (B,C,H,W)
    transpose_kernel<<<dim3(12, 98, 32), dim3(32, 8)>>>(attn, out, H_ * W_, C_);
}